// round 2
// baseline (speedup 1.0000x reference)
#include <cuda_runtime.h>
#include <cstdint>
#include <math.h>

#define BB 128      // batch
#define SS 4096     // seq
#define DD 256      // value/query dim
#define UU 128      // units
#define SPLITS 4
#define CHUNK (SS/SPLITS)     // 1024
#define TILE 32
#define NTILES (CHUNK/TILE)   // 32
#define UPAD 132              // W2 smem row stride (bank-conflict-free)
#define VPAD 260              // values smem row stride

// -------- scratch (no allocations allowed) --------
__device__ float g_qb[BB*UU];             // q@W1 + b1 + b2
__device__ float g_scores[BB*SS];         // raw scores
__device__ float g_pm[BB*SPLITS];         // per-chunk max
__device__ float g_ps[BB*SPLITS];         // per-chunk expsum
__device__ float g_pctx[BB*SPLITS*DD];    // per-chunk unnormalized context
__device__ float g_m[BB];                 // global max
__device__ float g_inv[BB];               // 1/sum

__device__ __forceinline__ uint32_t tf32_rna(float x) {
    uint32_t r;
    asm("cvt.rna.tf32.f32 %0, %1;" : "=r"(r) : "f"(x));
    return r;
}

// ---------------- kernel 1: q_proj = query @ W1 + b1 + b2 ----------------
__global__ void qproj_kernel(const float* __restrict__ query,
                             const float* __restrict__ W1,
                             const float* __restrict__ b1,
                             const float* __restrict__ b2) {
    __shared__ float q[DD];
    int b = blockIdx.x, u = threadIdx.x;      // 128 threads
    q[u]       = query[b*DD + u];
    q[u + 128] = query[b*DD + u + 128];
    __syncthreads();
    float acc = b1[u] + b2[u];
    #pragma unroll 8
    for (int d = 0; d < DD; d++) acc += q[d] * W1[d*UU + u];
    g_qb[b*UU + u] = acc;
}

// ---------------- kernel 2: main fused pass ----------------
// grid (SPLITS, BB), 256 threads. Single read of `values`:
// v_proj (tf32 MMA) -> tanh -> score -> online softmax + context accumulate.
extern __shared__ float smem[];

__global__ void __launch_bounds__(256, 1)
attn_main(const float* __restrict__ values,
          const float* __restrict__ W2,
          const float* __restrict__ Wv) {
    float* W2s   = smem;                       // [256][UPAD] tf32-rounded
    float* valsb = W2s + DD*UPAD;              // 2 x [TILE][VPAD]
    float* qb    = valsb + 2*TILE*VPAD;        // [128]
    float* wv    = qb + UU;                    // [128]
    float* spart = wv + UU;                    // [4][32] partial row sums
    float* sp    = spart + UU;                 // [32] softmax p values
    float* sctx  = sp + TILE;                  // [256] running context
    float* sred  = sctx + DD;                  // [0]=scale

    const int b = blockIdx.y, split = blockIdx.x;
    const int s0 = split * CHUNK;
    const int tid = threadIdx.x;
    const int lane = tid & 31, wid = tid >> 5;
    const int wr = wid >> 2, wc = wid & 3;     // warp row(2) x col(4): 16x32 warp tile
    const int g = lane >> 2, t = lane & 3;

    // stage W2 (round-to-nearest tf32 once)
    for (int i = tid; i < DD*UU; i += 256) {
        int r = i >> 7, c = i & 127;
        uint32_t v = tf32_rna(W2[i]);
        W2s[r*UPAD + c] = __uint_as_float(v);
    }
    if (tid < UU) { qb[tid] = g_qb[b*UU + tid]; wv[tid] = Wv[tid]; }
    sctx[tid] = 0.f;

    // async tile loader: 32 rows x 256 floats, 8 x 16B per thread
    auto load_tile = [&](int tile, int bufsel) {
        const float* src = values + (((size_t)b*SS + s0 + tile*TILE) * DD);
        float* dst = valsb + bufsel*TILE*VPAD;
        #pragma unroll
        for (int j = 0; j < 8; j++) {
            int c = tid + j*256;               // 0..2047
            int row = c >> 6, col = (c & 63) << 2;
            uint32_t daddr = (uint32_t)__cvta_generic_to_shared(dst + row*VPAD + col);
            const float* s = src + row*DD + col;
            asm volatile("cp.async.cg.shared.global [%0], [%1], 16;" :: "r"(daddr), "l"(s));
        }
        asm volatile("cp.async.commit_group;");
    };

    load_tile(0, 0);
    float m_run = -INFINITY, s_run = 0.f;      // tracked consistently by all of warp 0

    for (int tile = 0; tile < NTILES; ++tile) {
        int buf = tile & 1;
        asm volatile("cp.async.wait_group 0;");
        __syncthreads();
        if (tile + 1 < NTILES) load_tile(tile + 1, buf ^ 1);

        const float* va = valsb + buf*TILE*VPAD;

        // ---- GEMM: v_proj tile [32 x 128] via m16n8k8 tf32 ----
        float acc[4][4];
        #pragma unroll
        for (int i = 0; i < 4; i++)
            #pragma unroll
            for (int j = 0; j < 4; j++) acc[i][j] = 0.f;

        #pragma unroll 4
        for (int kk = 0; kk < 32; ++kk) {
            const int k0 = kk * 8;
            uint32_t a0 = tf32_rna(va[(wr*16 + g    )*VPAD + k0 + t    ]);
            uint32_t a1 = tf32_rna(va[(wr*16 + 8 + g)*VPAD + k0 + t    ]);
            uint32_t a2 = tf32_rna(va[(wr*16 + g    )*VPAD + k0 + t + 4]);
            uint32_t a3 = tf32_rna(va[(wr*16 + 8 + g)*VPAD + k0 + t + 4]);
            #pragma unroll
            for (int nf = 0; nf < 4; ++nf) {
                const int u0 = wc*32 + nf*8;
                uint32_t b0 = __float_as_uint(W2s[(k0 + t    )*UPAD + u0 + g]);
                uint32_t b1 = __float_as_uint(W2s[(k0 + t + 4)*UPAD + u0 + g]);
                asm volatile(
                    "mma.sync.aligned.m16n8k8.row.col.f32.tf32.tf32.f32 "
                    "{%0,%1,%2,%3}, {%4,%5,%6,%7}, {%8,%9}, {%0,%1,%2,%3};"
                    : "+f"(acc[nf][0]), "+f"(acc[nf][1]), "+f"(acc[nf][2]), "+f"(acc[nf][3])
                    : "r"(a0), "r"(a1), "r"(a2), "r"(a3), "r"(b0), "r"(b1));
            }
        }

        // ---- epilogue: tanh -> dot Wv -> per-row score ----
        float sumA = 0.f, sumB = 0.f;
        #pragma unroll
        for (int nf = 0; nf < 4; ++nf) {
            const int c0 = wc*32 + nf*8 + 2*t, c1 = c0 + 1;
            sumA += tanhf(acc[nf][0] + qb[c0]) * wv[c0];
            sumA += tanhf(acc[nf][1] + qb[c1]) * wv[c1];
            sumB += tanhf(acc[nf][2] + qb[c0]) * wv[c0];
            sumB += tanhf(acc[nf][3] + qb[c1]) * wv[c1];
        }
        sumA += __shfl_xor_sync(0xffffffffu, sumA, 1);
        sumA += __shfl_xor_sync(0xffffffffu, sumA, 2);
        sumB += __shfl_xor_sync(0xffffffffu, sumB, 1);
        sumB += __shfl_xor_sync(0xffffffffu, sumB, 2);
        if (t == 0) {
            spart[wc*32 + wr*16 + g]     = sumA;
            spart[wc*32 + wr*16 + 8 + g] = sumB;
        }
        __syncthreads();

        if (wid == 0) {
            float sc = spart[lane] + spart[32 + lane] + spart[64 + lane] + spart[96 + lane];
            g_scores[(size_t)b*SS + s0 + tile*TILE + lane] = sc;
            float mt = sc;
            #pragma unroll
            for (int o = 16; o; o >>= 1) mt = fmaxf(mt, __shfl_xor_sync(0xffffffffu, mt, o));
            float m_new = fmaxf(m_run, mt);
            float scale = expf(m_run - m_new);     // first tile: exp(-inf) = 0
            float p = expf(sc - m_new);
            sp[lane] = p;
            float psum = p;
            #pragma unroll
            for (int o = 16; o; o >>= 1) psum += __shfl_xor_sync(0xffffffffu, psum, o);
            s_run = s_run * scale + psum;
            m_run = m_new;
            if (lane == 0) sred[0] = scale;
        }
        __syncthreads();

        // ---- context accumulate: ctx[d] = ctx[d]*scale + sum_r p[r]*vals[r][d] ----
        {
            float c = sctx[tid] * sred[0];
            #pragma unroll 8
            for (int r = 0; r < TILE; ++r)
                c += sp[r] * va[r*VPAD + tid];
            sctx[tid] = c;
        }
    }

    const int pi = b*SPLITS + split;
    if (tid == 0) { g_pm[pi] = m_run; g_ps[pi] = s_run; }
    g_pctx[pi*DD + tid] = sctx[tid];
}

// ---------------- kernel 3: merge split partials -> context ----------------
__global__ void merge_kernel(float* __restrict__ out_ctx) {
    int b = blockIdx.x, tid = threadIdx.x;    // 256 threads
    __shared__ float pm[SPLITS], ps[SPLITS];
    if (tid < SPLITS) { pm[tid] = g_pm[b*SPLITS + tid]; ps[tid] = g_ps[b*SPLITS + tid]; }
    __syncthreads();
    float mg = pm[0];
    #pragma unroll
    for (int i = 1; i < SPLITS; i++) mg = fmaxf(mg, pm[i]);
    float w[SPLITS], sg = 0.f;
    #pragma unroll
    for (int i = 0; i < SPLITS; i++) { w[i] = expf(pm[i] - mg); sg += ps[i] * w[i]; }
    float inv = 1.f / sg;
    float c = 0.f;
    #pragma unroll
    for (int i = 0; i < SPLITS; i++) c += g_pctx[(b*SPLITS + i)*DD + tid] * w[i];
    out_ctx[b*DD + tid] = c * inv;
    if (tid == 0) { g_m[b] = mg; g_inv[b] = inv; }
}

// ---------------- kernel 4: normalized attention weights ----------------
__global__ void weights_kernel(float* __restrict__ out_w) {
    int i = blockIdx.x * blockDim.x + threadIdx.x;  // B*S total
    int b = i >> 12;
    out_w[i] = expf(g_scores[i] - g_m[b]) * g_inv[b];
}

extern "C" void kernel_launch(void* const* d_in, const int* in_sizes, int n_in,
                              void* d_out, int out_size) {
    const float* query  = (const float*)d_in[0];
    const float* values = (const float*)d_in[1];
    const float* W1     = (const float*)d_in[2];
    const float* b1     = (const float*)d_in[3];
    const float* W2     = (const float*)d_in[4];
    const float* b2     = (const float*)d_in[5];
    const float* Wv     = (const float*)d_in[6];
    // d_in[7] = bv: constant over seq -> cancels in softmax; context/weights unaffected.
    float* out = (float*)d_out;

    qproj_kernel<<<BB, UU>>>(query, W1, b1, b2);

    size_t smem_bytes = (size_t)(DD*UPAD + 2*TILE*VPAD + UU + UU + UU + TILE + DD + 8) * sizeof(float);
    cudaFuncSetAttribute(attn_main, cudaFuncAttributeMaxDynamicSharedMemorySize, (int)smem_bytes);
    attn_main<<<dim3(SPLITS, BB), 256, smem_bytes>>>(values, W2, Wv);

    merge_kernel<<<BB, DD>>>(out);                       // context -> out[0 : 32768)
    weights_kernel<<<(BB*SS)/256, 256>>>(out + BB*DD);   // weights -> out[32768 : )
}

// round 5
// speedup vs baseline: 1.3965x; 1.3965x over previous
#include <cuda_runtime.h>
#include <cstdint>
#include <math.h>

#define BB 128      // batch
#define SS 4096     // seq
#define DD 256      // value/query dim
#define UU 128      // units
#define SPLITS 8
#define CHUNK (SS/SPLITS)     // 512
#define TILE 64
#define NTILES (CHUNK/TILE)   // 8
#define VPAD 260              // values smem row stride (conflict-free)

// -------- scratch (no allocations allowed) --------
__device__ float g_qb[BB*UU];             // q@W1 + b1 + b2
__device__ float g_scores[BB*SS];         // exp(score), unnormalized
__device__ float g_ps[BB*SPLITS];         // per-chunk expsum
__device__ float g_pctx[BB*SPLITS*DD];    // per-chunk unnormalized context
__device__ float g_inv[BB];               // 1/sum

__device__ __forceinline__ uint32_t tf32_rna(float x) {
    uint32_t r;
    asm("cvt.rna.tf32.f32 %0, %1;" : "=r"(r) : "f"(x));
    return r;
}

// ---------------- kernel 1: q_proj = query @ W1 + b1 + b2 ----------------
__global__ void qproj_kernel(const float* __restrict__ query,
                             const float* __restrict__ W1,
                             const float* __restrict__ b1,
                             const float* __restrict__ b2) {
    __shared__ float q[DD];
    int b = blockIdx.x, u = threadIdx.x;      // 128 threads
    q[u]       = query[b*DD + u];
    q[u + 128] = query[b*DD + u + 128];
    __syncthreads();
    float acc = b1[u] + b2[u];
    #pragma unroll 8
    for (int d = 0; d < DD; d++) acc += q[d] * W1[d*UU + u];
    g_qb[b*UU + u] = acc;
}

// ---------------- kernel 2: main fused pass ----------------
// grid (SPLITS, BB), 256 threads. Single read of `values`.
// A-operand (W2^T) lives ENTIRELY in registers (128 regs/thread), loaded once.
// B-operand = values fragments from SMEM. Scores are tanh-bounded (|s|<~9),
// so exp() needs no max subtraction -> no online softmax, no serial section.
extern __shared__ float smem[];

__global__ void __launch_bounds__(256, 1)
attn_main(const float* __restrict__ values,
          const float* __restrict__ W2,
          const float* __restrict__ Wv) {
    float* valsb = smem;                        // 2 x [TILE][VPAD]
    float* spart = valsb + 2*TILE*VPAD;         // [8 warps][64 cols]
    float* sp    = spart + 8*64;                // [64] exp(score) per row
    float* sred  = sp + 64;                     // [2]

    const int b = blockIdx.y, split = blockIdx.x;
    const int s0 = split * CHUNK;
    const int tid = threadIdx.x;
    const int lane = tid & 31, wid = tid >> 5;
    const int g = lane >> 2, t = lane & 3;
    const int u0 = wid * 16;                    // each warp owns 16 units

    // async tile loader: 64 rows x 256 floats, 16 x 16B per thread
    auto load_tile = [&](int tile, int bufsel) {
        const float* src = values + (((size_t)b*SS + s0 + tile*TILE) * DD);
        float* dst = valsb + bufsel*TILE*VPAD;
        #pragma unroll
        for (int p = 0; p < 16; p++) {
            int e = p*1024 + tid*4;
            int row = e >> 8, col = e & 255;
            uint32_t da = (uint32_t)__cvta_generic_to_shared(dst + row*VPAD + col);
            asm volatile("cp.async.cg.shared.global [%0], [%1], 16;"
                         :: "r"(da), "l"(src + row*DD + col));
        }
        asm volatile("cp.async.commit_group;");
    };
    load_tile(0, 0);

    // ---- A fragments: W2^T rows [u0, u0+16), all K=256, tf32-rounded, in regs ----
    uint32_t Af[32][4];
    #pragma unroll
    for (int kk = 0; kk < 32; kk++) {
        const float* w = W2 + (kk*8 + t) * UU;     // row k = 8kk+t of W2[d][u]
        Af[kk][0] = tf32_rna(w[u0 + g]);
        Af[kk][1] = tf32_rna(w[u0 + 8 + g]);
        Af[kk][2] = tf32_rna(w[4*UU + u0 + g]);    // row k = 8kk+t+4
        Af[kk][3] = tf32_rna(w[4*UU + u0 + 8 + g]);
    }
    const float qbg = g_qb[b*UU + u0 + g], qb8 = g_qb[b*UU + u0 + 8 + g];
    const float wvg = Wv[u0 + g],          wv8 = Wv[u0 + 8 + g];

    float cacc = 0.f;     // running context for d = tid
    float sacc = 0.f;     // exp-sum partial (threads < 64)

    for (int tile = 0; tile < NTILES; ++tile) {
        const int buf = tile & 1;
        asm volatile("cp.async.wait_group 0;");
        __syncthreads();
        if (tile + 1 < NTILES) load_tile(tile + 1, buf ^ 1);
        const float* va = valsb + buf*TILE*VPAD;

        // ---- 8 chunks of 8 seq rows: D[u][n] = W2^T @ values^T ----
        #pragma unroll 1
        for (int c = 0; c < 8; c++) {
            const int n0 = c * 8;
            float a0 = 0.f, a1 = 0.f, a2 = 0.f, a3 = 0.f;
            const float* br = va + (n0 + g) * VPAD;
            #pragma unroll
            for (int kk = 0; kk < 32; kk++) {
                uint32_t b0v = tf32_rna(br[kk*8 + t]);
                uint32_t b1v = tf32_rna(br[kk*8 + t + 4]);
                asm volatile(
                    "mma.sync.aligned.m16n8k8.row.col.f32.tf32.tf32.f32 "
                    "{%0,%1,%2,%3}, {%4,%5,%6,%7}, {%8,%9}, {%0,%1,%2,%3};"
                    : "+f"(a0), "+f"(a1), "+f"(a2), "+f"(a3)
                    : "r"(Af[kk][0]), "r"(Af[kk][1]), "r"(Af[kk][2]), "r"(Af[kk][3]),
                      "r"(b0v), "r"(b1v));
            }
            // epilogue: tanh -> *Wv -> reduce over units (g-lanes), per seq col
            float e0 = tanhf(a0 + qbg) * wvg;   // rows u0+g,   col n0+2t
            float e1 = tanhf(a1 + qbg) * wvg;   //              col n0+2t+1
            float e2 = tanhf(a2 + qb8) * wv8;   // rows u0+8+g, col n0+2t
            float e3 = tanhf(a3 + qb8) * wv8;
            float sc0 = e0 + e2, sc1 = e1 + e3;
            #pragma unroll
            for (int o = 4; o <= 16; o <<= 1) {
                sc0 += __shfl_xor_sync(0xffffffffu, sc0, o);
                sc1 += __shfl_xor_sync(0xffffffffu, sc1, o);
            }
            if (lane < 4) {
                spart[wid*64 + n0 + 2*lane    ] = sc0;
                spart[wid*64 + n0 + 2*lane + 1] = sc1;
            }
        }
        __syncthreads();

        // ---- cross-warp score reduce + exp (no max needed: |score| <= ~9) ----
        if (tid < 64) {
            float sc = 0.f;
            #pragma unroll
            for (int w = 0; w < 8; w++) sc += spart[w*64 + tid];
            float p = __expf(sc);
            sp[tid] = p;
            sacc += p;
            g_scores[(size_t)b*SS + s0 + tile*TILE + tid] = p;
        }
        __syncthreads();

        // ---- context accumulate: ctx[d] += sum_r p[r] * vals[r][d] ----
        float csum = cacc;
        #pragma unroll 8
        for (int r = 0; r < TILE; ++r)
            csum += sp[r] * va[r*VPAD + tid];
        cacc = csum;
    }

    // reduce exp-sum (nonzero only in warps 0,1)
    #pragma unroll
    for (int o = 16; o >= 1; o >>= 1) sacc += __shfl_xor_sync(0xffffffffu, sacc, o);
    if (lane == 0 && wid < 2) sred[wid] = sacc;
    __syncthreads();
    const int pi = b*SPLITS + split;
    if (tid == 0) g_ps[pi] = sred[0] + sred[1];
    g_pctx[pi*DD + tid] = cacc;
}

// ---------------- kernel 3: merge split partials -> context ----------------
__global__ void merge_kernel(float* __restrict__ out_ctx) {
    int b = blockIdx.x, tid = threadIdx.x;    // 256 threads
    __shared__ float sinv;
    if (tid == 0) {
        float s = 0.f;
        #pragma unroll
        for (int i = 0; i < SPLITS; i++) s += g_ps[b*SPLITS + i];
        float inv = 1.f / s;
        sinv = inv;
        g_inv[b] = inv;
    }
    __syncthreads();
    float c = 0.f;
    #pragma unroll
    for (int i = 0; i < SPLITS; i++) c += g_pctx[(b*SPLITS + i)*DD + tid];
    out_ctx[b*DD + tid] = c * sinv;
}

// ---------------- kernel 4: normalized attention weights ----------------
__global__ void weights_kernel(float* __restrict__ out_w) {
    int i = blockIdx.x * blockDim.x + threadIdx.x;  // B*S total
    int b = i >> 12;
    out_w[i] = g_scores[i] * g_inv[b];
}

extern "C" void kernel_launch(void* const* d_in, const int* in_sizes, int n_in,
                              void* d_out, int out_size) {
    const float* query  = (const float*)d_in[0];
    const float* values = (const float*)d_in[1];
    const float* W1     = (const float*)d_in[2];
    const float* b1     = (const float*)d_in[3];
    const float* W2     = (const float*)d_in[4];
    const float* b2     = (const float*)d_in[5];
    const float* Wv     = (const float*)d_in[6];
    // d_in[7] = bv: constant over seq -> cancels in softmax.
    float* out = (float*)d_out;

    qproj_kernel<<<BB, UU>>>(query, W1, b1, b2);

    size_t smem_bytes = (size_t)(2*TILE*VPAD + 8*64 + 64 + 8) * sizeof(float);
    cudaFuncSetAttribute(attn_main, cudaFuncAttributeMaxDynamicSharedMemorySize, (int)smem_bytes);
    attn_main<<<dim3(SPLITS, BB), 256, smem_bytes>>>(values, W2, Wv);

    merge_kernel<<<BB, DD>>>(out);                       // context -> out[0 : 32768)
    weights_kernel<<<(BB*SS)/256, 256>>>(out + BB*DD);   // weights -> out[32768 : )
}

// round 8
// speedup vs baseline: 1.6216x; 1.1612x over previous
#include <cuda_runtime.h>
#include <cstdint>
#include <math.h>

#define BB 128      // batch
#define SS 4096     // seq
#define DD 256      // value/query dim
#define UU 128      // units
#define SPLITS 8
#define CHUNK (SS/SPLITS)     // 512
#define TILE 64
#define NTILES (CHUNK/TILE)   // 8
#define VPAD 260              // values smem row stride (conflict-free: bank 4g+t)

// -------- scratch (no allocations allowed) --------
__device__ float g_qb[BB*UU];             // q@W1 + b1 + b2
__device__ float g_scores[BB*SS];         // exp(score), unnormalized
__device__ float g_ps[BB*SPLITS];         // per-chunk expsum
__device__ float g_pctx[BB*SPLITS*DD];    // per-chunk unnormalized context
__device__ float g_inv[BB];               // 1/sum

__device__ __forceinline__ uint32_t tf32_rna(float x) {
    uint32_t r;
    asm("cvt.rna.tf32.f32 %0, %1;" : "=r"(r) : "f"(x));
    return r;
}

#define MMA4(A0,A1,A2,A3, AF, B0, B1)                                          \
    asm volatile(                                                              \
        "mma.sync.aligned.m16n8k8.row.col.f32.tf32.tf32.f32 "                  \
        "{%0,%1,%2,%3}, {%4,%5,%6,%7}, {%8,%9}, {%0,%1,%2,%3};"                \
        : "+f"(A0), "+f"(A1), "+f"(A2), "+f"(A3)                               \
        : "r"((AF)[0]), "r"((AF)[1]), "r"((AF)[2]), "r"((AF)[3]),              \
          "r"(B0), "r"(B1))

// ---------------- kernel 1: q_proj = query @ W1 + b1 + b2 ----------------
__global__ void qproj_kernel(const float* __restrict__ query,
                             const float* __restrict__ W1,
                             const float* __restrict__ b1,
                             const float* __restrict__ b2) {
    __shared__ float q[DD];
    int b = blockIdx.x, u = threadIdx.x;      // 128 threads
    q[u]       = query[b*DD + u];
    q[u + 128] = query[b*DD + u + 128];
    __syncthreads();
    float acc = b1[u] + b2[u];
    #pragma unroll 8
    for (int d = 0; d < DD; d++) acc += q[d] * W1[d*UU + u];
    g_qb[b*UU + u] = acc;
}

// ---------------- kernel 2: main fused pass ----------------
// grid (SPLITS, BB), 256 threads. Single read of `values`.
// A (W2^T) entirely in registers. 4 independent MMA accumulator chains per
// warp (2 n-chunks x 2 K-halves) to hide HMMA latency.
extern __shared__ float smem[];

__global__ void __launch_bounds__(256, 1)
attn_main(const float* __restrict__ values,
          const float* __restrict__ W2,
          const float* __restrict__ Wv) {
    float* valsb = smem;                        // 2 x [TILE][VPAD]
    float* spart = valsb + 2*TILE*VPAD;         // [8 warps][64 cols]
    float* sp    = spart + 8*64;                // [64] exp(score) per row
    float* sred  = sp + 64;                     // [2]

    const int b = blockIdx.y, split = blockIdx.x;
    const int s0 = split * CHUNK;
    const int tid = threadIdx.x;
    const int lane = tid & 31, wid = tid >> 5;
    const int g = lane >> 2, t = lane & 3;
    const int u0 = wid * 16;                    // each warp owns 16 units

    // async tile loader: 64 rows x 256 floats, 16 x 16B per thread
    auto load_tile = [&](int tile, int bufsel) {
        const float* src = values + (((size_t)b*SS + s0 + tile*TILE) * DD);
        float* dst = valsb + bufsel*TILE*VPAD;
        #pragma unroll
        for (int p = 0; p < 16; p++) {
            int e = p*1024 + tid*4;
            int row = e >> 8, col = e & 255;
            uint32_t da = (uint32_t)__cvta_generic_to_shared(dst + row*VPAD + col);
            asm volatile("cp.async.cg.shared.global [%0], [%1], 16;"
                         :: "r"(da), "l"(src + row*DD + col));
        }
        asm volatile("cp.async.commit_group;");
    };
    load_tile(0, 0);

    // ---- A fragments: W2^T rows [u0, u0+16), all K=256, tf32-rounded, regs ----
    uint32_t Af[32][4];
    #pragma unroll
    for (int kk = 0; kk < 32; kk++) {
        const float* w = W2 + (kk*8 + t) * UU;     // row k = 8kk+t of W2[d][u]
        Af[kk][0] = tf32_rna(w[u0 + g]);
        Af[kk][1] = tf32_rna(w[u0 + 8 + g]);
        Af[kk][2] = tf32_rna(w[4*UU + u0 + g]);    // row k = 8kk+t+4
        Af[kk][3] = tf32_rna(w[4*UU + u0 + 8 + g]);
    }
    const float qbg = g_qb[b*UU + u0 + g], qb8 = g_qb[b*UU + u0 + 8 + g];
    const float wvg = Wv[u0 + g],          wv8 = Wv[u0 + 8 + g];

    float cacc = 0.f;     // running context for d = tid
    float sacc = 0.f;     // exp-sum partial (threads < 64)

    for (int tile = 0; tile < NTILES; ++tile) {
        const int buf = tile & 1;
        asm volatile("cp.async.wait_group 0;");
        __syncthreads();
        if (tile + 1 < NTILES) load_tile(tile + 1, buf ^ 1);
        const float* va = valsb + buf*TILE*VPAD;

        // ---- 4 chunk-pairs of 16 seq rows: D[u][n] = W2^T @ values^T ----
        #pragma unroll 1
        for (int c = 0; c < 4; c++) {
            const int n0 = c * 16;
            // 4 independent chains: [chunk(2)][khalf(2)], 4 accs each
            float acc[2][2][4];
            #pragma unroll
            for (int i = 0; i < 2; i++)
                #pragma unroll
                for (int j = 0; j < 2; j++)
                    #pragma unroll
                    for (int k = 0; k < 4; k++) acc[i][j][k] = 0.f;

            const float* brA = va + (n0 + g) * VPAD;       // seq rows n0..n0+7
            const float* brB = brA + 8 * VPAD;             // seq rows n0+8..n0+15
            #pragma unroll
            for (int kk = 0; kk < 16; kk++) {
                uint32_t bA0  = tf32_rna(brA[kk*8 + t]);
                uint32_t bA1  = tf32_rna(brA[kk*8 + t + 4]);
                uint32_t bB0  = tf32_rna(brB[kk*8 + t]);
                uint32_t bB1  = tf32_rna(brB[kk*8 + t + 4]);
                uint32_t bA0h = tf32_rna(brA[(kk+16)*8 + t]);
                uint32_t bA1h = tf32_rna(brA[(kk+16)*8 + t + 4]);
                uint32_t bB0h = tf32_rna(brB[(kk+16)*8 + t]);
                uint32_t bB1h = tf32_rna(brB[(kk+16)*8 + t + 4]);
                MMA4(acc[0][0][0], acc[0][0][1], acc[0][0][2], acc[0][0][3], Af[kk],    bA0,  bA1);
                MMA4(acc[1][0][0], acc[1][0][1], acc[1][0][2], acc[1][0][3], Af[kk],    bB0,  bB1);
                MMA4(acc[0][1][0], acc[0][1][1], acc[0][1][2], acc[0][1][3], Af[kk+16], bA0h, bA1h);
                MMA4(acc[1][1][0], acc[1][1][1], acc[1][1][2], acc[1][1][3], Af[kk+16], bB0h, bB1h);
            }

            // combine K-halves, epilogue per chunk: tanh -> *Wv -> unit reduce
            #pragma unroll
            for (int ch = 0; ch < 2; ch++) {
                float a0 = acc[ch][0][0] + acc[ch][1][0];
                float a1 = acc[ch][0][1] + acc[ch][1][1];
                float a2 = acc[ch][0][2] + acc[ch][1][2];
                float a3 = acc[ch][0][3] + acc[ch][1][3];
                float e0 = tanhf(a0 + qbg) * wvg;   // units u0+g,   col n0+8ch+2t
                float e1 = tanhf(a1 + qbg) * wvg;   //               col n0+8ch+2t+1
                float e2 = tanhf(a2 + qb8) * wv8;   // units u0+8+g, col n0+8ch+2t
                float e3 = tanhf(a3 + qb8) * wv8;
                float sc0 = e0 + e2, sc1 = e1 + e3;
                #pragma unroll
                for (int o = 4; o <= 16; o <<= 1) {
                    sc0 += __shfl_xor_sync(0xffffffffu, sc0, o);
                    sc1 += __shfl_xor_sync(0xffffffffu, sc1, o);
                }
                if (lane < 4) {
                    spart[wid*64 + n0 + 8*ch + 2*lane    ] = sc0;
                    spart[wid*64 + n0 + 8*ch + 2*lane + 1] = sc1;
                }
            }
        }
        __syncthreads();

        // ---- cross-warp score reduce + exp (tanh-bounded: no max needed) ----
        if (tid < 64) {
            float sc = 0.f;
            #pragma unroll
            for (int w = 0; w < 8; w++) sc += spart[w*64 + tid];
            float p = __expf(sc);
            sp[tid] = p;
            sacc += p;
            g_scores[(size_t)b*SS + s0 + tile*TILE + tid] = p;
        }
        __syncthreads();

        // ---- context accumulate: ctx[d] += sum_r p[r] * vals[r][d] ----
        float csum = cacc;
        #pragma unroll 8
        for (int r = 0; r < TILE; ++r)
            csum += sp[r] * va[r*VPAD + tid];
        cacc = csum;
    }

    // reduce exp-sum (nonzero only in warps 0,1)
    #pragma unroll
    for (int o = 16; o >= 1; o >>= 1) sacc += __shfl_xor_sync(0xffffffffu, sacc, o);
    if (lane == 0 && wid < 2) sred[wid] = sacc;
    __syncthreads();
    const int pi = b*SPLITS + split;
    if (tid == 0) g_ps[pi] = sred[0] + sred[1];
    g_pctx[pi*DD + tid] = cacc;
}

// ---------------- kernel 3: merge split partials -> context ----------------
__global__ void merge_kernel(float* __restrict__ out_ctx) {
    int b = blockIdx.x, tid = threadIdx.x;    // 256 threads
    __shared__ float sinv;
    if (tid == 0) {
        float s = 0.f;
        #pragma unroll
        for (int i = 0; i < SPLITS; i++) s += g_ps[b*SPLITS + i];
        float inv = 1.f / s;
        sinv = inv;
        g_inv[b] = inv;
    }
    __syncthreads();
    float c = 0.f;
    #pragma unroll
    for (int i = 0; i < SPLITS; i++) c += g_pctx[(b*SPLITS + i)*DD + tid];
    out_ctx[b*DD + tid] = c * sinv;
}

// ---------------- kernel 4: normalized attention weights ----------------
__global__ void weights_kernel(float* __restrict__ out_w) {
    int i = blockIdx.x * blockDim.x + threadIdx.x;  // B*S total
    int b = i >> 12;
    out_w[i] = g_scores[i] * g_inv[b];
}

extern "C" void kernel_launch(void* const* d_in, const int* in_sizes, int n_in,
                              void* d_out, int out_size) {
    const float* query  = (const float*)d_in[0];
    const float* values = (const float*)d_in[1];
    const float* W1     = (const float*)d_in[2];
    const float* b1     = (const float*)d_in[3];
    const float* W2     = (const float*)d_in[4];
    const float* b2     = (const float*)d_in[5];
    const float* Wv     = (const float*)d_in[6];
    // d_in[7] = bv: constant over seq -> cancels in softmax.
    float* out = (float*)d_out;

    qproj_kernel<<<BB, UU>>>(query, W1, b1, b2);

    size_t smem_bytes = (size_t)(2*TILE*VPAD + 8*64 + 64 + 8) * sizeof(float);
    cudaFuncSetAttribute(attn_main, cudaFuncAttributeMaxDynamicSharedMemorySize, (int)smem_bytes);
    attn_main<<<dim3(SPLITS, BB), 256, smem_bytes>>>(values, W2, Wv);

    merge_kernel<<<BB, DD>>>(out);                       // context -> out[0 : 32768)
    weights_kernel<<<(BB*SS)/256, 256>>>(out + BB*DD);   // weights -> out[32768 : )
}